// round 3
// baseline (speedup 1.0000x reference)
#include <cuda_runtime.h>
#include <cuda_bf16.h>
#include <cstdint>

// ---------------------------------------------------------------------------
// DiffNet forward, CSR-gather formulation (no float atomics):
//   build CSR(S), CSR(R) per call (hist -> scan -> fill)
//   layer: agg = S @ U (warp-per-row gather)  ;  U = relu([agg,U] @ W + b)
//   G = U2 + R @ V ; out = [G[bu]; V[bp]; V[bn]]
// ---------------------------------------------------------------------------

#define D 64
#define NU 100000
#define MAXS 3300000
#define MAXR 5200000

__device__ float g_agg[NU * D];
__device__ float g_u1 [NU * D];
__device__ float g_u2 [NU * D];
__device__ float g_g  [NU * D];

__device__ int2 g_edgeS[MAXS];          // {col, float-bits val}
__device__ int2 g_edgeR[MAXR];
__device__ int  g_startS[NU + 1];
__device__ int  g_startR[NU + 1];
__device__ int  g_curS[NU];
__device__ int  g_curR[NU];
__device__ int  g_cnt[NU];

// ---------------------------------------------------------------------------
__global__ void zero_int_kernel(int* __restrict__ p, int n) {
    int i = blockIdx.x * blockDim.x + threadIdx.x;
    if (i < n) p[i] = 0;
}

__global__ void hist_kernel(const int* __restrict__ row, int nnz, int* __restrict__ cnt) {
    int i = blockIdx.x * blockDim.x + threadIdx.x;
    if (i < nnz) atomicAdd(cnt + __ldg(row + i), 1);
}

// Single-block exclusive scan over cnt[0..n), writes start[0..n] and cursor copy.
__global__ __launch_bounds__(1024)
void scan_kernel(const int* __restrict__ cnt, int n,
                 int* __restrict__ start, int* __restrict__ cursor) {
    __shared__ int part[1024];
    int tid = threadIdx.x;
    int chunk = (n + 1023) >> 10;
    int lo = tid * chunk;
    int hi = min(lo + chunk, n);
    int s = 0;
    for (int i = lo; i < hi; i++) s += cnt[i];
    part[tid] = s;
    __syncthreads();
    // Hillis-Steele inclusive scan
    for (int d = 1; d < 1024; d <<= 1) {
        int v = (tid >= d) ? part[tid - d] : 0;
        __syncthreads();
        part[tid] += v;
        __syncthreads();
    }
    int off = tid ? part[tid - 1] : 0;
    for (int i = lo; i < hi; i++) {
        start[i] = off; cursor[i] = off;
        off += cnt[i];
    }
    if (hi == n && lo <= n) start[n] = tid ? part[1023] : part[1023]; // total
}

__global__ void fill_kernel(const int* __restrict__ row, const int* __restrict__ col,
                            const float* __restrict__ val, int nnz,
                            int* __restrict__ cursor, int2* __restrict__ edges) {
    int i = blockIdx.x * blockDim.x + threadIdx.x;
    if (i >= nnz) return;
    int r = __ldg(row + i);
    int p = atomicAdd(cursor + r, 1);
    edges[p] = make_int2(__ldg(col + i), __float_as_int(__ldg(val + i)));
}

// Warp-per-row gather SpMM: Y[r] = (addin ? addin[r] : 0) + sum_e val*X[col].
// Lane l owns floats [2l, 2l+1] of the 64-wide row. 4-edge unroll for MLP.
__global__ __launch_bounds__(256)
void spmm_csr_kernel(const int* __restrict__ start, const int2* __restrict__ edges,
                     const float* __restrict__ X, const float* __restrict__ addin,
                     float* __restrict__ Y, int nrows) {
    int gw   = (blockIdx.x * blockDim.x + threadIdx.x) >> 5;
    int lane = threadIdx.x & 31;
    if (gw >= nrows) return;
    int s = __ldg(start + gw);
    int e = __ldg(start + gw + 1);
    float a0 = 0.f, a1 = 0.f;
    int j = s;
    for (; j + 4 <= e; j += 4) {
        int2 e0 = __ldg(edges + j);
        int2 e1 = __ldg(edges + j + 1);
        int2 e2 = __ldg(edges + j + 2);
        int2 e3 = __ldg(edges + j + 3);
        float2 x0 = *reinterpret_cast<const float2*>(X + (long long)e0.x * D + lane * 2);
        float2 x1 = *reinterpret_cast<const float2*>(X + (long long)e1.x * D + lane * 2);
        float2 x2 = *reinterpret_cast<const float2*>(X + (long long)e2.x * D + lane * 2);
        float2 x3 = *reinterpret_cast<const float2*>(X + (long long)e3.x * D + lane * 2);
        float v0 = __int_as_float(e0.y), v1 = __int_as_float(e1.y);
        float v2 = __int_as_float(e2.y), v3 = __int_as_float(e3.y);
        a0 = fmaf(v0, x0.x, a0); a1 = fmaf(v0, x0.y, a1);
        a0 = fmaf(v1, x1.x, a0); a1 = fmaf(v1, x1.y, a1);
        a0 = fmaf(v2, x2.x, a0); a1 = fmaf(v2, x2.y, a1);
        a0 = fmaf(v3, x3.x, a0); a1 = fmaf(v3, x3.y, a1);
    }
    for (; j < e; j++) {
        int2 ee = __ldg(edges + j);
        float2 x = *reinterpret_cast<const float2*>(X + (long long)ee.x * D + lane * 2);
        float v = __int_as_float(ee.y);
        a0 = fmaf(v, x.x, a0); a1 = fmaf(v, x.y, a1);
    }
    if (addin) {
        float2 ad = *reinterpret_cast<const float2*>(addin + (long long)gw * D + lane * 2);
        a0 += ad.x; a1 += ad.y;
    }
    *reinterpret_cast<float2*>(Y + (long long)gw * D + lane * 2) = make_float2(a0, a1);
}

// out[r] = relu( concat(A[r], Uin[r]) @ W + b ), W: [128,64].
__global__ __launch_bounds__(256)
void dense_kernel(const float* __restrict__ A,
                  const float* __restrict__ Uin,
                  const float* __restrict__ W,
                  const float* __restrict__ b,
                  float* __restrict__ out,
                  int nrows) {
    __shared__ float Ws[2 * D * D];     // 32 KB
    __shared__ float bs[D];
    __shared__ float xs[8][2][2 * D];

    int tid = threadIdx.x;
    for (int i = tid; i < 2 * D * D; i += 256) Ws[i] = W[i];
    if (tid < D) bs[tid] = b[tid];
    __syncthreads();

    int warp = tid >> 5, lane = tid & 31;
    int subrow = lane >> 4;
    int cg     = lane & 15;

    for (int base = blockIdx.x * 16; base < nrows; base += gridDim.x * 16) {
        #pragma unroll
        for (int it = 0; it < 2; it++) {
            int slot = it * 32 + lane;
            int rr   = slot >> 5;
            int off  = (slot & 31) * 4;
            int rowg = base + warp * 2 + rr;
            float4 vv;
            if (off < D) vv = *reinterpret_cast<const float4*>(A   + (long long)rowg * D + off);
            else         vv = *reinterpret_cast<const float4*>(Uin + (long long)rowg * D + (off - D));
            *reinterpret_cast<float4*>(&xs[warp][rr][off]) = vv;
        }
        __syncwarp();

        float4 acc = *reinterpret_cast<const float4*>(&bs[cg * 4]);
        const float* xr = xs[warp][subrow];
        #pragma unroll 8
        for (int k = 0; k < 2 * D; k++) {
            float xk = xr[k];
            float4 w = *reinterpret_cast<const float4*>(&Ws[k * D + cg * 4]);
            acc.x = fmaf(xk, w.x, acc.x);
            acc.y = fmaf(xk, w.y, acc.y);
            acc.z = fmaf(xk, w.z, acc.z);
            acc.w = fmaf(xk, w.w, acc.w);
        }
        acc.x = fmaxf(acc.x, 0.f); acc.y = fmaxf(acc.y, 0.f);
        acc.z = fmaxf(acc.z, 0.f); acc.w = fmaxf(acc.w, 0.f);
        int r = base + warp * 2 + subrow;
        *reinterpret_cast<float4*>(out + (long long)r * D + cg * 4) = acc;
        __syncwarp();
    }
}

__global__ void gather_kernel(const int* __restrict__ bu,
                              const int* __restrict__ bp,
                              const int* __restrict__ bn,
                              const float* __restrict__ G,
                              const float* __restrict__ V,
                              float* __restrict__ out,
                              int B) {
    int i = blockIdx.x * blockDim.x + threadIdx.x;
    int total = 3 * B * 16;
    if (i >= total) return;
    int sec  = i / (B * 16);
    int rem  = i - sec * (B * 16);
    int r    = rem >> 4;
    int lane = rem & 15;
    const float* src;
    if (sec == 0)      src = G + (long long)__ldg(bu + r) * D;
    else if (sec == 1) src = V + (long long)__ldg(bp + r) * D;
    else               src = V + (long long)__ldg(bn + r) * D;
    reinterpret_cast<float4*>(out)[i] =
        *reinterpret_cast<const float4*>(src + lane * 4);
}

// ---------------------------------------------------------------------------
extern "C" void kernel_launch(void* const* d_in, const int* in_sizes, int n_in,
                              void* d_out, int out_size) {
    const int*   bu    = (const int*)  d_in[0];
    const int*   bp    = (const int*)  d_in[1];
    const int*   bn    = (const int*)  d_in[2];
    const float* U     = (const float*)d_in[3];
    const float* V     = (const float*)d_in[4];
    const float* W0    = (const float*)d_in[5];
    const float* b0    = (const float*)d_in[6];
    const float* W1    = (const float*)d_in[7];
    const float* b1    = (const float*)d_in[8];
    const int*   S_row = (const int*)  d_in[9];
    const int*   S_col = (const int*)  d_in[10];
    const float* S_val = (const float*)d_in[11];
    const int*   R_row = (const int*)  d_in[12];
    const int*   R_col = (const int*)  d_in[13];
    const float* R_val = (const float*)d_in[14];

    int B       = in_sizes[0];
    int n_users = in_sizes[3] / D;
    int s_nnz   = in_sizes[9];
    int r_nnz   = in_sizes[12];

    float *agg, *u1, *u2, *gg;
    int *startS, *startR, *curS, *curR, *cnt;
    int2 *edgeS, *edgeR;
    cudaGetSymbolAddress((void**)&agg,    g_agg);
    cudaGetSymbolAddress((void**)&u1,     g_u1);
    cudaGetSymbolAddress((void**)&u2,     g_u2);
    cudaGetSymbolAddress((void**)&gg,     g_g);
    cudaGetSymbolAddress((void**)&startS, g_startS);
    cudaGetSymbolAddress((void**)&startR, g_startR);
    cudaGetSymbolAddress((void**)&curS,   g_curS);
    cudaGetSymbolAddress((void**)&curR,   g_curR);
    cudaGetSymbolAddress((void**)&cnt,    g_cnt);
    cudaGetSymbolAddress((void**)&edgeS,  g_edgeS);
    cudaGetSymbolAddress((void**)&edgeR,  g_edgeR);

    int zb  = (n_users + 255) / 256;
    int sb  = (s_nnz + 255) / 256;
    int rb  = (r_nnz + 255) / 256;
    int wb  = (n_users * 32 + 255) / 256;   // warp-per-row grid

    // --- Build CSR(S) ---
    zero_int_kernel<<<zb, 256>>>(cnt, n_users);
    hist_kernel<<<sb, 256>>>(S_row, s_nnz, cnt);
    scan_kernel<<<1, 1024>>>(cnt, n_users, startS, curS);
    fill_kernel<<<sb, 256>>>(S_row, S_col, S_val, s_nnz, curS, edgeS);
    // --- Build CSR(R) ---
    zero_int_kernel<<<zb, 256>>>(cnt, n_users);
    hist_kernel<<<rb, 256>>>(R_row, r_nnz, cnt);
    scan_kernel<<<1, 1024>>>(cnt, n_users, startR, curR);
    fill_kernel<<<rb, 256>>>(R_row, R_col, R_val, r_nnz, curR, edgeR);

    const int DENSE_BLOCKS = 592;

    // Layer 0
    spmm_csr_kernel<<<wb, 256>>>(startS, edgeS, U, nullptr, agg, n_users);
    dense_kernel<<<DENSE_BLOCKS, 256>>>(agg, U, W0, b0, u1, n_users);
    // Layer 1
    spmm_csr_kernel<<<wb, 256>>>(startS, edgeS, u1, nullptr, agg, n_users);
    dense_kernel<<<DENSE_BLOCKS, 256>>>(agg, u1, W1, b1, u2, n_users);
    // G = U2 + R @ V
    spmm_csr_kernel<<<wb, 256>>>(startR, edgeR, V, u2, gg, n_users);
    // Gather outputs
    int g_total  = 3 * B * 16;
    int g_blocks = (g_total + 255) / 256;
    gather_kernel<<<g_blocks, 256>>>(bu, bp, bn, gg, V, (float*)d_out, B);
}

// round 4
// speedup vs baseline: 1.3159x; 1.3159x over previous
#include <cuda_runtime.h>
#include <cuda_bf16.h>
#include <cstdint>

// ---------------------------------------------------------------------------
// DiffNet forward, batch-sparsified:
//   CSR(S) build once.
//   Layer0 (full):  s1 = S@U (CSR gather), s2 = relu([s1,U]@W0+b0)
//   Layer1 (batch): aggB[i] = (S@s2)[bu[i]],  gB[i] = relu([aggB,s2[bu]]@W1+b1)
//   R (batch):      gB[map[r]] += val * V[col]   (masked COO scatter, vec4 red)
//   out = [gB[map[bu]]; V[bp]; V[bn]]
// ---------------------------------------------------------------------------

#define D 64
#define NU 100000
#define MAXS 3300000
#define BMAX 8192

__device__ float g_s1[NU * D];          // agg scratch (full)
__device__ float g_s2[NU * D];          // u1 (full)
__device__ float g_aggB[BMAX * D];      // batch agg
__device__ float g_gB  [BMAX * D];      // batch output rows
__device__ int2  g_edgeS[MAXS];         // {col, float-bits val}
__device__ int   g_startS[NU + 1];
__device__ int   g_curS[NU];
__device__ int   g_cnt[NU];
__device__ int   g_map[NU];             // user -> canonical batch slot (INT_MAX if absent)

// ---------------------------------------------------------------------------
__global__ void set_int_kernel(int* __restrict__ p, int n, int v) {
    int i = blockIdx.x * blockDim.x + threadIdx.x;
    if (i < n) p[i] = v;
}

__global__ void hist_kernel(const int* __restrict__ row, int nnz, int* __restrict__ cnt) {
    int i = blockIdx.x * blockDim.x + threadIdx.x;
    if (i < nnz) atomicAdd(cnt + __ldg(row + i), 1);
}

__global__ __launch_bounds__(1024)
void scan_kernel(const int* __restrict__ cnt, int n,
                 int* __restrict__ start, int* __restrict__ cursor) {
    __shared__ int part[1024];
    int tid = threadIdx.x;
    int chunk = (n + 1023) >> 10;
    int lo = min(tid * chunk, n);
    int hi = min(lo + chunk, n);
    int s = 0;
    for (int i = lo; i < hi; i++) s += cnt[i];
    part[tid] = s;
    __syncthreads();
    for (int d = 1; d < 1024; d <<= 1) {
        int v = (tid >= d) ? part[tid - d] : 0;
        __syncthreads();
        part[tid] += v;
        __syncthreads();
    }
    int off = tid ? part[tid - 1] : 0;
    for (int i = lo; i < hi; i++) {
        start[i] = off; cursor[i] = off;
        off += cnt[i];
    }
    if (hi == n && lo < n) start[n] = part[1023];
}

__global__ void fill_kernel(const int* __restrict__ row, const int* __restrict__ col,
                            const float* __restrict__ val, int nnz,
                            int* __restrict__ cursor, int2* __restrict__ edges) {
    int i = blockIdx.x * blockDim.x + threadIdx.x;
    if (i >= nnz) return;
    int r = __ldg(row + i);
    int p = atomicAdd(cursor + r, 1);
    edges[p] = make_int2(__ldg(col + i), __float_as_int(__ldg(val + i)));
}

// map[user] = min batch index with that user
__global__ void map_build_kernel(const int* __restrict__ bu, int B, int* __restrict__ map) {
    int i = blockIdx.x * blockDim.x + threadIdx.x;
    if (i < B) atomicMin(map + __ldg(bu + i), i);
}

// Warp-per-row CSR gather spmm over ALL rows: Y[r] = sum val*X[col]
__global__ __launch_bounds__(256)
void spmm_full_kernel(const int* __restrict__ start, const int2* __restrict__ edges,
                      const float* __restrict__ X, float* __restrict__ Y, int nrows) {
    int gw   = (blockIdx.x * blockDim.x + threadIdx.x) >> 5;
    int lane = threadIdx.x & 31;
    if (gw >= nrows) return;
    int s = __ldg(start + gw);
    int e = __ldg(start + gw + 1);
    float a0 = 0.f, a1 = 0.f;
    int j = s;
    for (; j + 4 <= e; j += 4) {
        int2 e0 = __ldg(edges + j);
        int2 e1 = __ldg(edges + j + 1);
        int2 e2 = __ldg(edges + j + 2);
        int2 e3 = __ldg(edges + j + 3);
        float2 x0 = *reinterpret_cast<const float2*>(X + (long long)e0.x * D + lane * 2);
        float2 x1 = *reinterpret_cast<const float2*>(X + (long long)e1.x * D + lane * 2);
        float2 x2 = *reinterpret_cast<const float2*>(X + (long long)e2.x * D + lane * 2);
        float2 x3 = *reinterpret_cast<const float2*>(X + (long long)e3.x * D + lane * 2);
        a0 = fmaf(__int_as_float(e0.y), x0.x, a0); a1 = fmaf(__int_as_float(e0.y), x0.y, a1);
        a0 = fmaf(__int_as_float(e1.y), x1.x, a0); a1 = fmaf(__int_as_float(e1.y), x1.y, a1);
        a0 = fmaf(__int_as_float(e2.y), x2.x, a0); a1 = fmaf(__int_as_float(e2.y), x2.y, a1);
        a0 = fmaf(__int_as_float(e3.y), x3.x, a0); a1 = fmaf(__int_as_float(e3.y), x3.y, a1);
    }
    for (; j < e; j++) {
        int2 ee = __ldg(edges + j);
        float2 x = *reinterpret_cast<const float2*>(X + (long long)ee.x * D + lane * 2);
        float v = __int_as_float(ee.y);
        a0 = fmaf(v, x.x, a0); a1 = fmaf(v, x.y, a1);
    }
    *reinterpret_cast<float2*>(Y + (long long)gw * D + lane * 2) = make_float2(a0, a1);
}

// Warp-per-batch-index CSR gather (rows = bu[i]); skips duplicate batch slots.
__global__ __launch_bounds__(256)
void spmm_batch_kernel(const int* __restrict__ start, const int2* __restrict__ edges,
                       const float* __restrict__ X, const int* __restrict__ bu,
                       const int* __restrict__ map, float* __restrict__ Y, int B) {
    int gw   = (blockIdx.x * blockDim.x + threadIdx.x) >> 5;
    int lane = threadIdx.x & 31;
    if (gw >= B) return;
    int r = __ldg(bu + gw);
    if (__ldg(map + r) != gw) return;   // only canonical slot computes
    int s = __ldg(start + r);
    int e = __ldg(start + r + 1);
    float a0 = 0.f, a1 = 0.f;
    for (int j = s; j < e; j++) {
        int2 ee = __ldg(edges + j);
        float2 x = *reinterpret_cast<const float2*>(X + (long long)ee.x * D + lane * 2);
        float v = __int_as_float(ee.y);
        a0 = fmaf(v, x.x, a0); a1 = fmaf(v, x.y, a1);
    }
    *reinterpret_cast<float2*>(Y + (long long)gw * D + lane * 2) = make_float2(a0, a1);
}

// out[r] = relu( concat(A[r], Uin[urow(r)]) @ W + b ), W: [128,64].
// If bu != nullptr, Uin row is bu[r] (batch mode), else r.
__global__ __launch_bounds__(256)
void dense_kernel(const float* __restrict__ A,
                  const float* __restrict__ Uin,
                  const int* __restrict__ bu,
                  const float* __restrict__ W,
                  const float* __restrict__ b,
                  float* __restrict__ out,
                  int nrows) {
    __shared__ float Ws[2 * D * D];
    __shared__ float bs[D];
    __shared__ float xs[8][2][2 * D];

    int tid = threadIdx.x;
    for (int i = tid; i < 2 * D * D; i += 256) Ws[i] = W[i];
    if (tid < D) bs[tid] = b[tid];
    __syncthreads();

    int warp = tid >> 5, lane = tid & 31;
    int subrow = lane >> 4;
    int cg     = lane & 15;

    for (int base = blockIdx.x * 16; base < nrows; base += gridDim.x * 16) {
        #pragma unroll
        for (int it = 0; it < 2; it++) {
            int slot = it * 32 + lane;
            int rr   = slot >> 5;
            int off  = (slot & 31) * 4;
            int rowg = base + warp * 2 + rr;
            float4 vv;
            if (off < D) {
                vv = *reinterpret_cast<const float4*>(A + (long long)rowg * D + off);
            } else {
                long long ur = bu ? (long long)__ldg(bu + rowg) : (long long)rowg;
                vv = *reinterpret_cast<const float4*>(Uin + ur * D + (off - D));
            }
            *reinterpret_cast<float4*>(&xs[warp][rr][off]) = vv;
        }
        __syncwarp();

        float4 acc = *reinterpret_cast<const float4*>(&bs[cg * 4]);
        const float* xr = xs[warp][subrow];
        #pragma unroll 8
        for (int k = 0; k < 2 * D; k++) {
            float xk = xr[k];
            float4 w = *reinterpret_cast<const float4*>(&Ws[k * D + cg * 4]);
            acc.x = fmaf(xk, w.x, acc.x);
            acc.y = fmaf(xk, w.y, acc.y);
            acc.z = fmaf(xk, w.z, acc.z);
            acc.w = fmaf(xk, w.w, acc.w);
        }
        acc.x = fmaxf(acc.x, 0.f); acc.y = fmaxf(acc.y, 0.f);
        acc.z = fmaxf(acc.z, 0.f); acc.w = fmaxf(acc.w, 0.f);
        int r = base + warp * 2 + subrow;
        *reinterpret_cast<float4*>(out + (long long)r * D + cg * 4) = acc;
        __syncwarp();
    }
}

// Masked COO scatter: for edges whose row is a batch user, gB[slot] += v * V[col].
// 16 threads per edge, one red.v4 each.
__global__ void r_scatter_kernel(const int* __restrict__ row,
                                 const int* __restrict__ col,
                                 const float* __restrict__ val,
                                 const float* __restrict__ V,
                                 const int* __restrict__ map,
                                 float* __restrict__ gB,
                                 int nnz, int B) {
    long long idx = (long long)blockIdx.x * blockDim.x + threadIdx.x;
    int e    = (int)(idx >> 4);
    int lane = (int)(idx & 15);
    if (e >= nnz) return;
    int r = __ldg(row + e);
    int slot = __ldg(map + r);
    if (slot >= B) return;              // not a batch user
    int   c = __ldg(col + e);
    float v = __ldg(val + e);
    float4 x = *reinterpret_cast<const float4*>(V + (long long)c * D + lane * 4);
    float* dst = gB + (long long)slot * D + lane * 4;
    asm volatile("red.global.add.v4.f32 [%0], {%1,%2,%3,%4};"
                 :: "l"(dst), "f"(v * x.x), "f"(v * x.y), "f"(v * x.z), "f"(v * x.w)
                 : "memory");
}

__global__ void gather_kernel(const int* __restrict__ bu,
                              const int* __restrict__ bp,
                              const int* __restrict__ bn,
                              const int* __restrict__ map,
                              const float* __restrict__ gB,
                              const float* __restrict__ V,
                              float* __restrict__ out,
                              int B) {
    int i = blockIdx.x * blockDim.x + threadIdx.x;
    int total = 3 * B * 16;
    if (i >= total) return;
    int sec  = i / (B * 16);
    int rem  = i - sec * (B * 16);
    int r    = rem >> 4;
    int lane = rem & 15;
    const float* src;
    if (sec == 0)      src = gB + (long long)__ldg(map + __ldg(bu + r)) * D;
    else if (sec == 1) src = V + (long long)__ldg(bp + r) * D;
    else               src = V + (long long)__ldg(bn + r) * D;
    reinterpret_cast<float4*>(out)[i] =
        *reinterpret_cast<const float4*>(src + lane * 4);
}

// ---------------------------------------------------------------------------
extern "C" void kernel_launch(void* const* d_in, const int* in_sizes, int n_in,
                              void* d_out, int out_size) {
    const int*   bu    = (const int*)  d_in[0];
    const int*   bp    = (const int*)  d_in[1];
    const int*   bn    = (const int*)  d_in[2];
    const float* U     = (const float*)d_in[3];
    const float* V     = (const float*)d_in[4];
    const float* W0    = (const float*)d_in[5];
    const float* b0    = (const float*)d_in[6];
    const float* W1    = (const float*)d_in[7];
    const float* b1    = (const float*)d_in[8];
    const int*   S_row = (const int*)  d_in[9];
    const int*   S_col = (const int*)  d_in[10];
    const float* S_val = (const float*)d_in[11];
    const int*   R_row = (const int*)  d_in[12];
    const int*   R_col = (const int*)  d_in[13];
    const float* R_val = (const float*)d_in[14];

    int B       = in_sizes[0];
    int n_users = in_sizes[3] / D;
    int s_nnz   = in_sizes[9];
    int r_nnz   = in_sizes[12];

    float *s1, *s2, *aggB, *gB;
    int *startS, *curS, *cnt, *map;
    int2 *edgeS;
    cudaGetSymbolAddress((void**)&s1,     g_s1);
    cudaGetSymbolAddress((void**)&s2,     g_s2);
    cudaGetSymbolAddress((void**)&aggB,   g_aggB);
    cudaGetSymbolAddress((void**)&gB,     g_gB);
    cudaGetSymbolAddress((void**)&startS, g_startS);
    cudaGetSymbolAddress((void**)&curS,   g_curS);
    cudaGetSymbolAddress((void**)&cnt,    g_cnt);
    cudaGetSymbolAddress((void**)&map,    g_map);
    cudaGetSymbolAddress((void**)&edgeS,  g_edgeS);

    int zb = (n_users + 255) / 256;
    int sb = (s_nnz + 255) / 256;
    int wb_full  = (n_users * 32 + 255) / 256;
    int wb_batch = (B * 32 + 255) / 256;

    // --- CSR(S) build + user->slot map (independent chains) ---
    set_int_kernel<<<zb, 256>>>(cnt, n_users, 0);
    set_int_kernel<<<zb, 256>>>(map, n_users, 0x7FFFFFFF);
    hist_kernel<<<sb, 256>>>(S_row, s_nnz, cnt);
    scan_kernel<<<1, 1024>>>(cnt, n_users, startS, curS);
    fill_kernel<<<sb, 256>>>(S_row, S_col, S_val, s_nnz, curS, edgeS);
    map_build_kernel<<<(B + 255) / 256, 256>>>(bu, B, map);

    const int DENSE_BLOCKS = 592;

    // --- Layer 0 (full) ---
    spmm_full_kernel<<<wb_full, 256>>>(startS, edgeS, U, s1, n_users);
    dense_kernel<<<DENSE_BLOCKS, 256>>>(s1, U, nullptr, W0, b0, s2, n_users);

    // --- Layer 1 (batch rows only) ---
    spmm_batch_kernel<<<wb_batch, 256>>>(startS, edgeS, s2, bu, map, aggB, B);
    dense_kernel<<<(B + 15) / 16, 256>>>(aggB, s2, bu, W1, b1, gB, B);

    // --- gB += masked R @ V ---
    long long rt = (long long)r_nnz * 16;
    r_scatter_kernel<<<(int)((rt + 255) / 256), 256>>>(R_row, R_col, R_val, V, map, gB, r_nnz, B);

    // --- Gather outputs ---
    int g_total  = 3 * B * 16;
    gather_kernel<<<(g_total + 255) / 256, 256>>>(bu, bp, bn, map, gB, V, (float*)d_out, B);
}

// round 5
// speedup vs baseline: 1.6064x; 1.2208x over previous
#include <cuda_runtime.h>
#include <cuda_bf16.h>
#include <cstdint>

// ---------------------------------------------------------------------------
// DiffNet forward, batch-sparsified, parallel CSR build:
//   CSR(S) build once (hist -> 3-phase parallel scan -> fill).
//   Layer0 (full):  s1 = S@U (CSR gather), s2 = relu([s1,U]@W0+b0)
//   Layer1 (batch): aggB[i] = (S@s2)[bu[i]],  gB[i] = relu([aggB,s2[bu]]@W1+b1)
//   R (batch):      gB[map[r]] += val * V[col]   (masked COO scatter, vec4 red)
//   out = [gB[map[bu]]; V[bp]; V[bn]]
// ---------------------------------------------------------------------------

#define D 64
#define NU 100000
#define MAXS 3300000
#define BMAX 8192
#define SCAN_B 1024
#define MAX_SCAN_BLOCKS 128

__device__ float g_s1[NU * D];
__device__ float g_s2[NU * D];
__device__ float g_aggB[BMAX * D];
__device__ float g_gB  [BMAX * D];
__device__ int2  g_edgeS[MAXS];
__device__ int   g_startS[NU + 1];
__device__ int   g_curS[NU];
__device__ int   g_cnt[NU];
__device__ int   g_map[NU];
__device__ int   g_bsum[MAX_SCAN_BLOCKS];

// ---------------------------------------------------------------------------
__global__ void set_int_kernel(int* __restrict__ p, int n, int v) {
    int i = blockIdx.x * blockDim.x + threadIdx.x;
    if (i < n) p[i] = v;
}

__global__ void hist_kernel(const int* __restrict__ row, int nnz, int* __restrict__ cnt) {
    int i = blockIdx.x * blockDim.x + threadIdx.x;
    if (i < nnz) atomicAdd(cnt + __ldg(row + i), 1);
}

// Phase 1: per-block smem scan; start[i] = local exclusive prefix; bsum[b] = block total.
__global__ __launch_bounds__(SCAN_B)
void scan_blocks_kernel(const int* __restrict__ cnt, int n,
                        int* __restrict__ start, int* __restrict__ bsum) {
    __shared__ int sh[SCAN_B];
    int tid = threadIdx.x;
    int i   = blockIdx.x * SCAN_B + tid;
    int v   = (i < n) ? cnt[i] : 0;
    sh[tid] = v;
    __syncthreads();
    #pragma unroll
    for (int d = 1; d < SCAN_B; d <<= 1) {
        int t = (tid >= d) ? sh[tid - d] : 0;
        __syncthreads();
        sh[tid] += t;
        __syncthreads();
    }
    if (i < n) start[i] = sh[tid] - v;       // exclusive (local)
    if (tid == SCAN_B - 1) bsum[blockIdx.x] = sh[tid];
}

// Phase 2: scan block totals in one small block; also writes start[n] = grand total.
__global__ __launch_bounds__(MAX_SCAN_BLOCKS)
void scan_tops_kernel(int* __restrict__ bsum, int nblocks, int* __restrict__ start, int n) {
    __shared__ int sh[MAX_SCAN_BLOCKS];
    int tid = threadIdx.x;
    int v = (tid < nblocks) ? bsum[tid] : 0;
    sh[tid] = v;
    __syncthreads();
    #pragma unroll
    for (int d = 1; d < MAX_SCAN_BLOCKS; d <<= 1) {
        int t = (tid >= d) ? sh[tid - d] : 0;
        __syncthreads();
        sh[tid] += t;
        __syncthreads();
    }
    if (tid < nblocks) bsum[tid] = sh[tid] - v;     // exclusive block offset
    if (tid == nblocks - 1) start[n] = sh[tid];     // grand total
}

// Phase 3: add block offsets; write cursor copy.
__global__ __launch_bounds__(SCAN_B)
void scan_addoff_kernel(int* __restrict__ start, const int* __restrict__ bsum,
                        int* __restrict__ cursor, int n) {
    int i = blockIdx.x * SCAN_B + threadIdx.x;
    if (i >= n) return;
    int s = start[i] + __ldg(bsum + blockIdx.x);
    start[i] = s;
    cursor[i] = s;
}

__global__ void fill_kernel(const int* __restrict__ row, const int* __restrict__ col,
                            const float* __restrict__ val, int nnz,
                            int* __restrict__ cursor, int2* __restrict__ edges) {
    int i = blockIdx.x * blockDim.x + threadIdx.x;
    if (i >= nnz) return;
    int r = __ldg(row + i);
    int p = atomicAdd(cursor + r, 1);
    edges[p] = make_int2(__ldg(col + i), __float_as_int(__ldg(val + i)));
}

__global__ void map_build_kernel(const int* __restrict__ bu, int B, int* __restrict__ map) {
    int i = blockIdx.x * blockDim.x + threadIdx.x;
    if (i < B) atomicMin(map + __ldg(bu + i), i);
}

// Warp-per-row CSR gather spmm over ALL rows.
__global__ __launch_bounds__(256)
void spmm_full_kernel(const int* __restrict__ start, const int2* __restrict__ edges,
                      const float* __restrict__ X, float* __restrict__ Y, int nrows) {
    int gw   = (blockIdx.x * blockDim.x + threadIdx.x) >> 5;
    int lane = threadIdx.x & 31;
    if (gw >= nrows) return;
    int s = __ldg(start + gw);
    int e = __ldg(start + gw + 1);
    float a0 = 0.f, a1 = 0.f;
    int j = s;
    for (; j + 4 <= e; j += 4) {
        int2 e0 = __ldg(edges + j);
        int2 e1 = __ldg(edges + j + 1);
        int2 e2 = __ldg(edges + j + 2);
        int2 e3 = __ldg(edges + j + 3);
        float2 x0 = *reinterpret_cast<const float2*>(X + (long long)e0.x * D + lane * 2);
        float2 x1 = *reinterpret_cast<const float2*>(X + (long long)e1.x * D + lane * 2);
        float2 x2 = *reinterpret_cast<const float2*>(X + (long long)e2.x * D + lane * 2);
        float2 x3 = *reinterpret_cast<const float2*>(X + (long long)e3.x * D + lane * 2);
        a0 = fmaf(__int_as_float(e0.y), x0.x, a0); a1 = fmaf(__int_as_float(e0.y), x0.y, a1);
        a0 = fmaf(__int_as_float(e1.y), x1.x, a0); a1 = fmaf(__int_as_float(e1.y), x1.y, a1);
        a0 = fmaf(__int_as_float(e2.y), x2.x, a0); a1 = fmaf(__int_as_float(e2.y), x2.y, a1);
        a0 = fmaf(__int_as_float(e3.y), x3.x, a0); a1 = fmaf(__int_as_float(e3.y), x3.y, a1);
    }
    for (; j < e; j++) {
        int2 ee = __ldg(edges + j);
        float2 x = *reinterpret_cast<const float2*>(X + (long long)ee.x * D + lane * 2);
        float v = __int_as_float(ee.y);
        a0 = fmaf(v, x.x, a0); a1 = fmaf(v, x.y, a1);
    }
    *reinterpret_cast<float2*>(Y + (long long)gw * D + lane * 2) = make_float2(a0, a1);
}

// Warp-per-batch-index CSR gather (rows = bu[i]); skips duplicate batch slots.
__global__ __launch_bounds__(256)
void spmm_batch_kernel(const int* __restrict__ start, const int2* __restrict__ edges,
                       const float* __restrict__ X, const int* __restrict__ bu,
                       const int* __restrict__ map, float* __restrict__ Y, int B) {
    int gw   = (blockIdx.x * blockDim.x + threadIdx.x) >> 5;
    int lane = threadIdx.x & 31;
    if (gw >= B) return;
    int r = __ldg(bu + gw);
    if (__ldg(map + r) != gw) return;
    int s = __ldg(start + r);
    int e = __ldg(start + r + 1);
    float a0 = 0.f, a1 = 0.f;
    for (int j = s; j < e; j++) {
        int2 ee = __ldg(edges + j);
        float2 x = *reinterpret_cast<const float2*>(X + (long long)ee.x * D + lane * 2);
        float v = __int_as_float(ee.y);
        a0 = fmaf(v, x.x, a0); a1 = fmaf(v, x.y, a1);
    }
    *reinterpret_cast<float2*>(Y + (long long)gw * D + lane * 2) = make_float2(a0, a1);
}

// out[r] = relu( concat(A[r], Uin[urow(r)]) @ W + b ), W: [128,64].
__global__ __launch_bounds__(256)
void dense_kernel(const float* __restrict__ A,
                  const float* __restrict__ Uin,
                  const int* __restrict__ bu,
                  const float* __restrict__ W,
                  const float* __restrict__ b,
                  float* __restrict__ out,
                  int nrows) {
    __shared__ float Ws[2 * D * D];
    __shared__ float bs[D];
    __shared__ float xs[8][2][2 * D];

    int tid = threadIdx.x;
    for (int i = tid; i < 2 * D * D; i += 256) Ws[i] = W[i];
    if (tid < D) bs[tid] = b[tid];
    __syncthreads();

    int warp = tid >> 5, lane = tid & 31;
    int subrow = lane >> 4;
    int cg     = lane & 15;

    for (int base = blockIdx.x * 16; base < nrows; base += gridDim.x * 16) {
        #pragma unroll
        for (int it = 0; it < 2; it++) {
            int slot = it * 32 + lane;
            int rr   = slot >> 5;
            int off  = (slot & 31) * 4;
            int rowg = base + warp * 2 + rr;
            float4 vv;
            if (off < D) {
                vv = *reinterpret_cast<const float4*>(A + (long long)rowg * D + off);
            } else {
                long long ur = bu ? (long long)__ldg(bu + rowg) : (long long)rowg;
                vv = *reinterpret_cast<const float4*>(Uin + ur * D + (off - D));
            }
            *reinterpret_cast<float4*>(&xs[warp][rr][off]) = vv;
        }
        __syncwarp();

        float4 acc = *reinterpret_cast<const float4*>(&bs[cg * 4]);
        const float* xr = xs[warp][subrow];
        #pragma unroll 8
        for (int k = 0; k < 2 * D; k++) {
            float xk = xr[k];
            float4 w = *reinterpret_cast<const float4*>(&Ws[k * D + cg * 4]);
            acc.x = fmaf(xk, w.x, acc.x);
            acc.y = fmaf(xk, w.y, acc.y);
            acc.z = fmaf(xk, w.z, acc.z);
            acc.w = fmaf(xk, w.w, acc.w);
        }
        acc.x = fmaxf(acc.x, 0.f); acc.y = fmaxf(acc.y, 0.f);
        acc.z = fmaxf(acc.z, 0.f); acc.w = fmaxf(acc.w, 0.f);
        int r = base + warp * 2 + subrow;
        *reinterpret_cast<float4*>(out + (long long)r * D + cg * 4) = acc;
        __syncwarp();
    }
}

// Masked COO scatter for R into batch rows.
__global__ void r_scatter_kernel(const int* __restrict__ row,
                                 const int* __restrict__ col,
                                 const float* __restrict__ val,
                                 const float* __restrict__ V,
                                 const int* __restrict__ map,
                                 float* __restrict__ gB,
                                 int nnz, int B) {
    long long idx = (long long)blockIdx.x * blockDim.x + threadIdx.x;
    int e    = (int)(idx >> 4);
    int lane = (int)(idx & 15);
    if (e >= nnz) return;
    int r = __ldg(row + e);
    int slot = __ldg(map + r);
    if (slot >= B) return;
    int   c = __ldg(col + e);
    float v = __ldg(val + e);
    float4 x = *reinterpret_cast<const float4*>(V + (long long)c * D + lane * 4);
    float* dst = gB + (long long)slot * D + lane * 4;
    asm volatile("red.global.add.v4.f32 [%0], {%1,%2,%3,%4};"
                 :: "l"(dst), "f"(v * x.x), "f"(v * x.y), "f"(v * x.z), "f"(v * x.w)
                 : "memory");
}

__global__ void gather_kernel(const int* __restrict__ bu,
                              const int* __restrict__ bp,
                              const int* __restrict__ bn,
                              const int* __restrict__ map,
                              const float* __restrict__ gB,
                              const float* __restrict__ V,
                              float* __restrict__ out,
                              int B) {
    int i = blockIdx.x * blockDim.x + threadIdx.x;
    int total = 3 * B * 16;
    if (i >= total) return;
    int sec  = i / (B * 16);
    int rem  = i - sec * (B * 16);
    int r    = rem >> 4;
    int lane = rem & 15;
    const float* src;
    if (sec == 0)      src = gB + (long long)__ldg(map + __ldg(bu + r)) * D;
    else if (sec == 1) src = V + (long long)__ldg(bp + r) * D;
    else               src = V + (long long)__ldg(bn + r) * D;
    reinterpret_cast<float4*>(out)[i] =
        *reinterpret_cast<const float4*>(src + lane * 4);
}

// ---------------------------------------------------------------------------
extern "C" void kernel_launch(void* const* d_in, const int* in_sizes, int n_in,
                              void* d_out, int out_size) {
    const int*   bu    = (const int*)  d_in[0];
    const int*   bp    = (const int*)  d_in[1];
    const int*   bn    = (const int*)  d_in[2];
    const float* U     = (const float*)d_in[3];
    const float* V     = (const float*)d_in[4];
    const float* W0    = (const float*)d_in[5];
    const float* b0    = (const float*)d_in[6];
    const float* W1    = (const float*)d_in[7];
    const float* b1    = (const float*)d_in[8];
    const int*   S_row = (const int*)  d_in[9];
    const int*   S_col = (const int*)  d_in[10];
    const float* S_val = (const float*)d_in[11];
    const int*   R_row = (const int*)  d_in[12];
    const int*   R_col = (const int*)  d_in[13];
    const float* R_val = (const float*)d_in[14];

    int B       = in_sizes[0];
    int n_users = in_sizes[3] / D;
    int s_nnz   = in_sizes[9];
    int r_nnz   = in_sizes[12];

    float *s1, *s2, *aggB, *gB;
    int *startS, *curS, *cnt, *map, *bsum;
    int2 *edgeS;
    cudaGetSymbolAddress((void**)&s1,     g_s1);
    cudaGetSymbolAddress((void**)&s2,     g_s2);
    cudaGetSymbolAddress((void**)&aggB,   g_aggB);
    cudaGetSymbolAddress((void**)&gB,     g_gB);
    cudaGetSymbolAddress((void**)&startS, g_startS);
    cudaGetSymbolAddress((void**)&curS,   g_curS);
    cudaGetSymbolAddress((void**)&cnt,    g_cnt);
    cudaGetSymbolAddress((void**)&map,    g_map);
    cudaGetSymbolAddress((void**)&bsum,   g_bsum);
    cudaGetSymbolAddress((void**)&edgeS,  g_edgeS);

    int zb = (n_users + 255) / 256;
    int sb = (s_nnz + 255) / 256;
    int wb_full  = (n_users * 32 + 255) / 256;
    int wb_batch = (B * 32 + 255) / 256;
    int nscan = (n_users + SCAN_B - 1) / SCAN_B;   // <= MAX_SCAN_BLOCKS

    // --- CSR(S) build + user->slot map ---
    set_int_kernel<<<zb, 256>>>(cnt, n_users, 0);
    set_int_kernel<<<zb, 256>>>(map, n_users, 0x7FFFFFFF);
    hist_kernel<<<sb, 256>>>(S_row, s_nnz, cnt);
    scan_blocks_kernel<<<nscan, SCAN_B>>>(cnt, n_users, startS, bsum);
    scan_tops_kernel<<<1, MAX_SCAN_BLOCKS>>>(bsum, nscan, startS, n_users);
    scan_addoff_kernel<<<nscan, SCAN_B>>>(startS, bsum, curS, n_users);
    fill_kernel<<<sb, 256>>>(S_row, S_col, S_val, s_nnz, curS, edgeS);
    map_build_kernel<<<(B + 255) / 256, 256>>>(bu, B, map);

    const int DENSE_BLOCKS = 592;

    // --- Layer 0 (full) ---
    spmm_full_kernel<<<wb_full, 256>>>(startS, edgeS, U, s1, n_users);
    dense_kernel<<<DENSE_BLOCKS, 256>>>(s1, U, nullptr, W0, b0, s2, n_users);

    // --- Layer 1 (batch rows only) ---
    spmm_batch_kernel<<<wb_batch, 256>>>(startS, edgeS, s2, bu, map, aggB, B);
    dense_kernel<<<(B + 15) / 16, 256>>>(aggB, s2, bu, W1, b1, gB, B);

    // --- gB += masked R @ V ---
    long long rt = (long long)r_nnz * 16;
    r_scatter_kernel<<<(int)((rt + 255) / 256), 256>>>(R_row, R_col, R_val, V, map, gB, r_nnz, B);

    // --- Gather outputs ---
    int g_total  = 3 * B * 16;
    gather_kernel<<<(g_total + 255) / 256, 256>>>(bu, bp, bn, map, gB, V, (float*)d_out, B);
}